// round 16
// baseline (speedup 1.0000x reference)
#include <cuda_runtime.h>
#include <cuda_bf16.h>

__device__ float g_x3[4*3*256*256];
__device__ float g_x6[4*3*256*256];
__device__ float g_x9[4*3*256*256];
__device__ float g_xg[4];
// qkv scratch: P=2: 4*130*130 tiles * 12 hc * 12 floats; P=3: 4*88*88 * 6 * 36
__device__ float g_scr2[4*130*130*144];
__device__ float g_scr3[4*88*88*216];

__device__ __forceinline__ int reflect256(int t) {
    t = (t < 0) ? -t : t;
    return (t >= 256) ? (510 - t) : t;
}

__device__ __forceinline__ float ex2(float x) {
    float y; asm("ex2.approx.f32 %0, %1;" : "=f"(y) : "f"(x)); return y;
}

#define LOG2E 1.4426950408889634f

// exp(-t/P) as compile-time literals
template<int P>
__device__ __forceinline__ constexpr float ebias(int t) {
    return (t == 0) ? 1.0f
         : (t == 1) ? ((P == 2) ? 0.60653065971263342f : 0.71653131057378927f)
         : 0.51341711903259202f; // t==2 only for P==3
}

// stage 1: p=1, nh=6, bias==1. thread = (pixel, head); 32-pixel row block.
// one launch per batch (b passed in) so the profiler lands on attn1.
// also folds the per-batch max of x (g_xg) via atomicMax on float-as-int (x >= 0).
__global__ __launch_bounds__(192) void attn1_kernel(
    const float* __restrict__ X, const float* __restrict__ W,
    const float* __restrict__ B, const float* __restrict__ HW, int b)
{
    __shared__ float sxr[3][3][34];   // [c][row][col]
    __shared__ float sred[6][96];
    __shared__ float smax[6];

    const int bx = blockIdx.x;
    const int i  = bx >> 3;
    const int j0 = (bx & 7) * 32;
    const int tid = threadIdx.x;

    float lm = 0.f;
    for (int idx = tid; idx < 306; idx += 192) {
        int c = idx / 102, r2 = idx % 102, rr = r2 / 34, cc = r2 % 34;
        int y = reflect256(i + rr - 1), x2 = reflect256(j0 + cc - 1);
        float v = X[(b*3+c)*65536 + y*256 + x2];
        sxr[c][rr][cc] = v;
        lm = fmaxf(lm, v);
    }
    // block max -> atomic
    #pragma unroll
    for (int o = 16; o > 0; o >>= 1) lm = fmaxf(lm, __shfl_xor_sync(0xffffffffu, lm, o));
    if ((tid & 31) == 0) smax[tid >> 5] = lm;
    __syncthreads();
    if (tid == 0) {
        float v = fmaxf(fmaxf(fmaxf(smax[0], smax[1]), fmaxf(smax[2], smax[3])),
                        fmaxf(smax[4], smax[5]));
        atomicMax((int*)&g_xg[b], __float_as_int(v));
    }

    const int px = tid & 31, h = tid >> 5;

    float xn[9][3];
    #pragma unroll
    for (int k = 0; k < 9; k++)
        #pragma unroll
        for (int c = 0; c < 3; c++)
            xn[k][c] = sxr[c][k/3][px + k%3];

    const float rsl = 0.5773502691896258f * LOG2E; // (1/sqrt(3)) * log2(e)
    const float hw = __ldg(HW + h);

    #pragma unroll
    for (int c = 0; c < 3; c++) {
        int mq = (h*3+0)*3 + c, mk = (h*3+1)*3 + c, mv = (h*3+2)*3 + c;
        float q = __ldg(B+mq) + __ldg(W+mq*3+0)*xn[4][0]
                              + __ldg(W+mq*3+1)*xn[4][1]
                              + __ldg(W+mq*3+2)*xn[4][2];
        q *= rsl;
        // fold q into k-projection: p = ex2(qb + qw.x)
        float qb  = q*__ldg(B+mk);
        float qw0 = q*__ldg(W+mk*3+0), qw1 = q*__ldg(W+mk*3+1), qw2 = q*__ldg(W+mk*3+2);
        float S = 0.f, m0 = 0.f, m1 = 0.f, m2 = 0.f;
        #pragma unroll
        for (int k = 0; k < 9; k++) {
            float p = ex2(qb + qw0*xn[k][0] + qw1*xn[k][1] + qw2*xn[k][2]);
            S += p; m0 += p*xn[k][0]; m1 += p*xn[k][1]; m2 += p*xn[k][2];
        }
        // v via moments: sum p*(bv + wv.x) = bv*S + wv.(sum p*x)
        float o = __ldg(B+mv)*S + __ldg(W+mv*3+0)*m0
                + __ldg(W+mv*3+1)*m1 + __ldg(W+mv*3+2)*m2;
        sred[h][px*3 + c] = hw * __fdividef(o, S);
    }
    __syncthreads();

    if (tid < 96) {
        float s = 0.f;
        #pragma unroll
        for (int hh = 0; hh < 6; hh++) s += sred[hh][tid];
        int pxx = tid / 3, c = tid % 3;
        g_x3[(b*3+c)*65536 + i*256 + j0 + pxx] = s;
    }
}

// ---- stages 2/3: projection. warp handles WPH hc's sequentially, lane = tile. ----
// WPH=1 for P=2 (multi-wave grid), WPH=2 for P=3 (single-wave grid).
// Bias LDGs eliminated: P=3 folds bias into weight pad column (xr[27]=1);
// P=2 stages biases into smem.
template<int P, int NH, int WPH>
__global__ __launch_bounds__((NH*3/WPH)*32) void proj_kernel(
    const float* __restrict__ W, const float* __restrict__ B)
{
    constexpr int PP = P*P, L = 3*PP, HC = NH*3;
    constexpr int NWARPS = HC / WPH;
    constexpr int NT   = (P==2) ? 130 : 88;
    constexpr int PADL = (P==2) ? 2 : 5;
    constexpr int LW   = (P==2) ? 12 : 28;   // padded weight row (mult of 4)
    constexpr int SEC  = (P==2) ? 4 : 12;    // padded section length
    constexpr int HSTR = 3*SEC, TSTR = HC*HSTR;
    constexpr int MROW = NH*9*PP;            // total weight rows
    constexpr int NTILES = 4*NT*NT;
    constexpr int NTH = NWARPS*32;
    constexpr float RS = ((P==2) ? 0.2886751345948129f : 0.1924500897298753f) * LOG2E;

    __shared__ __align__(16) float swt[MROW*LW];
    __shared__ float sb[MROW];               // used only for P==2
    __shared__ float sxt[LW][32];            // transposed: [l][tile-lane]

    const float* Xg = (P==2) ? g_x3 : g_x6;
    float* scr      = (P==2) ? g_scr2 : g_scr3;

    const int tid = threadIdx.x;
    const int warp = tid >> 5, lane = tid & 31;
    const int t0 = blockIdx.x * 32;

    // weights into padded smem; for P==3 the pad column L(=27) carries the bias
    for (int idx = tid; idx < MROW*LW; idx += NTH) {
        int m = idx / LW, lp = idx % LW;
        float v = 0.f;
        if (lp < L) v = W[m*L + lp];
        else if (P == 3 && lp == L) v = B[m];
        swt[idx] = v;
    }
    if (P == 2) {
        for (int idx = tid; idx < MROW; idx += NTH) sb[idx] = B[idx];
    }
    // x tile rows, transposed so lane reads are conflict-free
    for (int idx = tid; idx < LW*32; idx += NTH) {
        int lp = idx >> 5, lane2 = idx & 31;
        int t = t0 + lane2;
        float v = 0.f;
        if (t < NTILES && lp < L) {
            int tj = t % NT, ti = (t / NT) % NT, b = t / (NT*NT);
            int cc = lp / PP, rr = (lp % PP) / P, ss = lp % P;
            int y  = reflect256(ti*P + rr - PADL);
            int x2 = reflect256(tj*P + ss - PADL);
            v = Xg[(b*3+cc)*65536 + y*256 + x2];
        }
        sxt[lp][lane2] = v;
    }
    __syncthreads();

    const int t = t0 + lane;
    const bool active = (t < NTILES);

    float xr[LW];
    #pragma unroll
    for (int l = 0; l < LW; l++) xr[l] = sxt[l][lane];
    if (P == 3) xr[L] = 1.0f;   // bias multiplier (weight pad column carries B)

    #pragma unroll
    for (int u = 0; u < WPH; u++) {
        const int hc = warp + u*NWARPS;
        const int h = hc % NH, c = hc / NH;
        float* outb = scr + (size_t)t*TSTR + hc*HSTR;

        #pragma unroll
        for (int sec = 0; sec < 3; sec++) {
            const int row0 = ((h*3 + sec)*3 + c)*PP;
            float acc[SEC];
            #pragma unroll
            for (int pos = 0; pos < SEC; pos++) acc[pos] = 0.f;
            #pragma unroll
            for (int pos = 0; pos < PP; pos++) {
                float a;
                if (P == 3) {
                    // 4 independent partial chains; bias rides chain 3 via xr[27]=1
                    float a0 = 0.f, a1 = 0.f, a2 = 0.f, a3 = 0.f;
                    #pragma unroll
                    for (int l4 = 0; l4 < LW/4; l4++) {
                        float4 w4 = *(const float4*)&swt[(row0+pos)*LW + l4*4];  // broadcast
                        a0 += w4.x*xr[l4*4+0];
                        a1 += w4.y*xr[l4*4+1];
                        a2 += w4.z*xr[l4*4+2];
                        a3 += w4.w*xr[l4*4+3];
                    }
                    a = (a0 + a1) + (a2 + a3);
                } else {
                    a = sb[row0 + pos];
                    #pragma unroll
                    for (int l4 = 0; l4 < LW/4; l4++) {
                        float4 w4 = *(const float4*)&swt[(row0+pos)*LW + l4*4];  // broadcast
                        a += w4.x*xr[l4*4+0] + w4.y*xr[l4*4+1]
                           + w4.z*xr[l4*4+2] + w4.w*xr[l4*4+3];
                    }
                }
                acc[pos] = (sec == 0) ? a*RS : a;
            }
            if (active) {
                #pragma unroll
                for (int s4 = 0; s4 < SEC/4; s4++) {
                    float4 o4;
                    o4.x = acc[s4*4+0]; o4.y = acc[s4*4+1];
                    o4.z = acc[s4*4+2]; o4.w = acc[s4*4+3];
                    *(float4*)&outb[sec*SEC + s4*4] = o4;
                }
            }
        }
    }
}

// ---- stages 2/3: attention kernel. block = 4x4 window patch, thread = (window, hc). ----
template<int P, int NH>
__global__ __launch_bounds__(16*NH*3) void attn_win_kernel(const float* __restrict__ HW)
{
    constexpr int PP = P*P, HC = NH*3;
    constexpr int NT   = (P==2) ? 130 : 88;
    constexpr int NHW  = (P==2) ? 128 : 86;
    constexpr int PADH = (P==2) ? 0 : 2;
    constexpr int SEC  = (P==2) ? 4 : 12;
    constexpr int HSTR = 3*SEC, TSTR = HC*HSTR;
    constexpr int NTH = 16*HC;

    __shared__ __align__(16) float st[36*TSTR];

    const float* scr = (P==2) ? g_scr2 : g_scr3;
    float* Og        = (P==2) ? g_x6 : g_x9;

    const int tid = threadIdx.x;
    const int wi0 = blockIdx.y * 4, wj0 = blockIdx.x * 4;
    const int b = blockIdx.z;

    // cooperative load of 6x6 tile qkv block (float4 granularity)
    for (int f4 = tid; f4 < 36*(TSTR/4); f4 += NTH) {
        int tile_l = f4 / (TSTR/4), rem = f4 % (TSTR/4);
        int u = tile_l / 6, v = tile_l % 6;
        int ti = wi0 + u, tj = wj0 + v;
        float4 val = make_float4(0.f, 0.f, 0.f, 0.f);
        if (ti < NT && tj < NT)
            val = *(const float4*)&scr[(size_t)((b*NT + ti)*NT + tj)*TSTR + rem*4];
        *(float4*)&st[tile_l*TSTR + rem*4] = val;
    }
    __syncthreads();

    const int hc = tid % HC, wl = tid / HC;
    const int h = hc % NH;
    const int c = hc / NH;
    const int wl4 = wl >> 2, wlm = wl & 3;
    const int wi = wi0 + wl4, wj = wj0 + wlm;
    const bool active = (wi < NHW) && (wj < NHW);

    // q of core tile (pre-scaled by log2e/sqrt(L))
    const float* core = st + ((wl4+1)*6 + (wlm+1))*TSTR + hc*HSTR;
    float q[SEC];
    #pragma unroll
    for (int s4 = 0; s4 < SEC/4; s4++)
        *(float4*)&q[s4*4] = *(const float4*)&core[s4*4];

    // qe[di][pos] = q[pos] * exp(-u/P), u = f(di, ii)
    float qe[3][PP];
    #pragma unroll
    for (int pos = 0; pos < PP; pos++) {
        const int ii = pos / P;
        qe[0][pos] = q[pos] * ebias<P>(P-1-ii);
        qe[1][pos] = q[pos];
        qe[2][pos] = q[pos] * ebias<P>(ii);
    }

    float score[9];
    #pragma unroll
    for (int k9 = 0; k9 < 9; k9++) {
        const int di = k9/3, dj = k9%3;
        const float* kt = st + ((wl4+di)*6 + (wlm+dj))*TSTR + hc*HSTR + SEC;
        float kv[SEC];
        #pragma unroll
        for (int s4 = 0; s4 < SEC/4; s4++)
            *(float4*)&kv[s4*4] = *(const float4*)&kt[s4*4];
        float s = 0.f;
        #pragma unroll
        for (int pos = 0; pos < PP; pos++) {
            const int jj = pos % P;
            const float ev = (dj==0) ? ebias<P>(P-1-jj) : ((dj==1) ? 1.f : ebias<P>(jj));
            s += qe[di][pos] * (ev * kv[pos]);
        }
        score[k9] = ex2(s);   // exp(raw score), log2e pre-folded into q
    }

    float sum = 0.f;
    #pragma unroll
    for (int k = 0; k < 9; k++) sum += score[k];
    const float hwv = __fdividef(__ldg(HW + h), sum);

    float outp[PP];
    #pragma unroll
    for (int pos = 0; pos < PP; pos++) outp[pos] = 0.f;
    #pragma unroll
    for (int k9 = 0; k9 < 9; k9++) {
        const float* vt = st + ((wl4 + k9/3)*6 + (wlm + k9%3))*TSTR + hc*HSTR + 2*SEC;
        float vv[SEC];
        #pragma unroll
        for (int s4 = 0; s4 < SEC/4; s4++)
            *(float4*)&vv[s4*4] = *(const float4*)&vt[s4*4];
        #pragma unroll
        for (int pos = 0; pos < PP; pos++) outp[pos] += score[k9] * vv[pos];
    }
    #pragma unroll
    for (int pos = 0; pos < PP; pos++) outp[pos] *= hwv;

    // head reduction over NH adjacent lanes (aligned groups)
    #pragma unroll
    for (int pos = 0; pos < PP; pos++) {
        outp[pos] += __shfl_xor_sync(0xffffffffu, outp[pos], 1);
        if (NH == 4) outp[pos] += __shfl_xor_sync(0xffffffffu, outp[pos], 2);
    }

    if (h == 0 && active) {
        #pragma unroll
        for (int pos = 0; pos < PP; pos++) {
            const int y  = wi*P + pos/P - PADH;
            const int x2 = wj*P + pos%P - PADH;
            if (y >= 0 && x2 >= 0)
                Og[(b*3+c)*65536 + y*256 + x2] = outp[pos];
        }
    }
}

// 5x5 conv (9->3 channels) fused with the final elementwise gate
__global__ __launch_bounds__(128) void conv_final_kernel(
    const float* __restrict__ X, const float* __restrict__ CW,
    const float* __restrict__ CB, float* __restrict__ out)
{
    __shared__ float sx[9][20][37];
    __shared__ float sw[675];
    __shared__ float sb[3];
    const int b = blockIdx.z;
    const int x0 = blockIdx.x * 32, y0 = blockIdx.y * 16;
    const int tid = threadIdx.x;

    for (int i2 = tid; i2 < 675; i2 += 128) sw[i2] = CW[i2];
    if (tid < 3) sb[tid] = CB[tid];
    for (int i2 = tid; i2 < 9*20*36; i2 += 128) {
        int ci = i2 / 720, rem = i2 % 720, yy = rem / 36, xx = rem % 36;
        int gy = y0 + yy - 2, gx = x0 + xx - 2;
        float v = 0.f;
        if ((unsigned)gy < 256u && (unsigned)gx < 256u) {
            const float* src = (ci < 3) ? g_x9 : ((ci < 6) ? g_x6 : g_x3);
            v = src[(b*3 + (ci % 3))*65536 + gy*256 + gx];
        }
        sx[ci][yy][xx] = v;
    }
    __syncthreads();

    const int tx = tid & 15, ty = tid >> 4;
    const int lx = tx*2, ly = ty*2;
    float acc[3][4];
    #pragma unroll
    for (int c2 = 0; c2 < 3; c2++)
        #pragma unroll
        for (int p2 = 0; p2 < 4; p2++) acc[c2][p2] = 0.f;

    #pragma unroll 1
    for (int ci = 0; ci < 9; ci++) {
        #pragma unroll
        for (int ky = 0; ky < 5; ky++) {
            #pragma unroll
            for (int kx = 0; kx < 5; kx++) {
                float w0 = sw[      ci*25 + ky*5 + kx];
                float w1 = sw[225 + ci*25 + ky*5 + kx];
                float w2 = sw[450 + ci*25 + ky*5 + kx];
                float a00 = sx[ci][ly+ky  ][lx+kx  ];
                float a01 = sx[ci][ly+ky  ][lx+kx+1];
                float a10 = sx[ci][ly+ky+1][lx+kx  ];
                float a11 = sx[ci][ly+ky+1][lx+kx+1];
                acc[0][0] += w0*a00; acc[0][1] += w0*a01; acc[0][2] += w0*a10; acc[0][3] += w0*a11;
                acc[1][0] += w1*a00; acc[1][1] += w1*a01; acc[1][2] += w1*a10; acc[1][3] += w1*a11;
                acc[2][0] += w2*a00; acc[2][1] += w2*a01; acc[2][2] += w2*a10; acc[2][3] += w2*a11;
            }
        }
    }

    const float xg = g_xg[b];
    #pragma unroll
    for (int co = 0; co < 3; co++) {
        #pragma unroll
        for (int py = 0; py < 2; py++) {
            #pragma unroll
            for (int px = 0; px < 2; px++) {
                int gy = y0 + ly + py, gx = x0 + lx + px;
                float x0v = fmaxf(acc[co][py*2+px] + sb[co], 0.f);
                float xv = X[(b*3+co)*65536 + gy*256 + gx];
                float r = fmaxf(xv * x0v + xg - x0v, 0.f);
                out[(b*3+co)*65536 + gy*256 + gx] = r;
            }
        }
    }
}

extern "C" void kernel_launch(void* const* d_in, const int* in_sizes, int n_in,
                              void* d_out, int out_size) {
    (void)in_sizes; (void)n_in; (void)out_size;
    const float* x   = (const float*)d_in[0];
    const float* w3  = (const float*)d_in[1];
    const float* b3  = (const float*)d_in[2];
    const float* hw3 = (const float*)d_in[3];
    const float* w6  = (const float*)d_in[4];
    const float* b6  = (const float*)d_in[5];
    const float* hw6 = (const float*)d_in[6];
    const float* w9  = (const float*)d_in[7];
    const float* b9  = (const float*)d_in[8];
    const float* hw9 = (const float*)d_in[9];
    const float* cw  = (const float*)d_in[10];
    const float* cb  = (const float*)d_in[11];
    float* out = (float*)d_out;

    // reset g_xg (x >= 0 so zero-init is a valid identity for max)
    void* xg_ptr = nullptr;
    cudaGetSymbolAddress(&xg_ptr, g_xg);
    cudaMemsetAsync(xg_ptr, 0, 4*sizeof(float));

    // stage 1: one launch per batch (puts attn1 at the profiled launch index)
    attn1_kernel<<<2048, 192>>>(x, w3, b3, hw3, 0);
    attn1_kernel<<<2048, 192>>>(x, w3, b3, hw3, 1);
    attn1_kernel<<<2048, 192>>>(x, w3, b3, hw3, 2);
    attn1_kernel<<<2048, 192>>>(x, w3, b3, hw3, 3);

    // stage 2: P=2, NH=4. 67600 tiles -> 2113 blocks of 32 tiles, 12 warps (WPH=1)
    proj_kernel<2, 4, 1><<<(67600 + 31) / 32, 12*32>>>(w6, b6);
    attn_win_kernel<2, 4><<<dim3(32, 32, 4), 16*12>>>(hw6);

    // stage 3: P=3, NH=2. 30976 tiles -> 968 blocks of 32 tiles, 3 warps (WPH=2)
    proj_kernel<3, 2, 2><<<30976/32, 3*32>>>(w9, b9);
    attn_win_kernel<3, 2><<<dim3(22, 22, 4), 16*6>>>(hw9);

    conv_final_kernel<<<dim3(8, 16, 4), 128>>>(x, cw, cb, out);
}

// round 17
// speedup vs baseline: 1.0306x; 1.0306x over previous
#include <cuda_runtime.h>
#include <cuda_bf16.h>

__device__ float g_x3[4*3*256*256];
__device__ float g_x6[4*3*256*256];
__device__ float g_x9[4*3*256*256];
__device__ float g_xg[4];
// qkv scratch: P=2: 4*130*130 tiles * 12 hc * 12 floats; P=3: 4*88*88 * 6 * 36
__device__ float g_scr2[4*130*130*144];
__device__ float g_scr3[4*88*88*216];

__device__ __forceinline__ int reflect256(int t) {
    t = (t < 0) ? -t : t;
    return (t >= 256) ? (510 - t) : t;
}

__device__ __forceinline__ float ex2(float x) {
    float y; asm("ex2.approx.f32 %0, %1;" : "=f"(y) : "f"(x)); return y;
}

#define LOG2E 1.4426950408889634f

// exp(-t/P) as compile-time literals
template<int P>
__device__ __forceinline__ constexpr float ebias(int t) {
    return (t == 0) ? 1.0f
         : (t == 1) ? ((P == 2) ? 0.60653065971263342f : 0.71653131057378927f)
         : 0.51341711903259202f; // t==2 only for P==3
}

// stage 1: p=1, nh=6, bias==1. thread = (pixel, head); 32-pixel row block.
// q folded into k-weights; v via moments. c-loop kept rolled to cap registers.
// also folds the per-batch max of x (g_xg) via atomicMax on float-as-int (x >= 0).
__global__ __launch_bounds__(192) void attn1_kernel(
    const float* __restrict__ X, const float* __restrict__ W,
    const float* __restrict__ B, const float* __restrict__ HW)
{
    __shared__ float sxr[3][3][34];   // [c][row][col]
    __shared__ float sred[6][96];
    __shared__ float smax[6];

    const int bx = blockIdx.x;
    const int b  = bx >> 11;          // 2048 blocks per batch
    const int i  = (bx >> 3) & 255;
    const int j0 = (bx & 7) * 32;
    const int tid = threadIdx.x;

    float lm = 0.f;
    for (int idx = tid; idx < 306; idx += 192) {
        int c = idx / 102, r2 = idx % 102, rr = r2 / 34, cc = r2 % 34;
        int y = reflect256(i + rr - 1), x2 = reflect256(j0 + cc - 1);
        float v = X[(b*3+c)*65536 + y*256 + x2];
        sxr[c][rr][cc] = v;
        lm = fmaxf(lm, v);
    }
    // block max -> atomic
    #pragma unroll
    for (int o = 16; o > 0; o >>= 1) lm = fmaxf(lm, __shfl_xor_sync(0xffffffffu, lm, o));
    if ((tid & 31) == 0) smax[tid >> 5] = lm;
    __syncthreads();
    if (tid == 0) {
        float v = fmaxf(fmaxf(fmaxf(smax[0], smax[1]), fmaxf(smax[2], smax[3])),
                        fmaxf(smax[4], smax[5]));
        atomicMax((int*)&g_xg[b], __float_as_int(v));
    }

    const int px = tid & 31, h = tid >> 5;

    float xn[9][3];
    #pragma unroll
    for (int k = 0; k < 9; k++)
        #pragma unroll
        for (int c = 0; c < 3; c++)
            xn[k][c] = sxr[c][k/3][px + k%3];

    const float rsl = 0.5773502691896258f * LOG2E; // (1/sqrt(3)) * log2(e)
    const float hw = __ldg(HW + h);

    #pragma unroll 1
    for (int c = 0; c < 3; c++) {
        int mq = (h*3+0)*3 + c, mk = (h*3+1)*3 + c, mv = (h*3+2)*3 + c;
        float q = __ldg(B+mq) + __ldg(W+mq*3+0)*xn[4][0]
                              + __ldg(W+mq*3+1)*xn[4][1]
                              + __ldg(W+mq*3+2)*xn[4][2];
        q *= rsl;
        // fold q into k-projection: p = ex2(qb + qw.x)
        float qb  = q*__ldg(B+mk);
        float qw0 = q*__ldg(W+mk*3+0), qw1 = q*__ldg(W+mk*3+1), qw2 = q*__ldg(W+mk*3+2);
        float S = 0.f, m0 = 0.f, m1 = 0.f, m2 = 0.f;
        #pragma unroll
        for (int k = 0; k < 9; k++) {
            float p = ex2(qb + qw0*xn[k][0] + qw1*xn[k][1] + qw2*xn[k][2]);
            S += p; m0 += p*xn[k][0]; m1 += p*xn[k][1]; m2 += p*xn[k][2];
        }
        // v via moments: sum p*(bv + wv.x) = bv*S + wv.(sum p*x)
        float o = __ldg(B+mv)*S + __ldg(W+mv*3+0)*m0
                + __ldg(W+mv*3+1)*m1 + __ldg(W+mv*3+2)*m2;
        sred[h][px*3 + c] = hw * __fdividef(o, S);
    }
    __syncthreads();

    if (tid < 96) {
        float s = 0.f;
        #pragma unroll
        for (int hh = 0; hh < 6; hh++) s += sred[hh][tid];
        int pxx = tid / 3, c = tid % 3;
        g_x3[(b*3+c)*65536 + i*256 + j0 + pxx] = s;
    }
}

// ---- stages 2/3: projection. warp handles WPH hc's sequentially, lane = tile. ----
// WPH=1 for P=2 (multi-wave grid), WPH=2 for P=3 (single-wave grid).
// Bias LDGs eliminated: P=3 folds bias into weight pad column (xr[27]=1);
// P=2 stages biases into smem.
template<int P, int NH, int WPH>
__global__ __launch_bounds__((NH*3/WPH)*32) void proj_kernel(
    const float* __restrict__ W, const float* __restrict__ B)
{
    constexpr int PP = P*P, L = 3*PP, HC = NH*3;
    constexpr int NWARPS = HC / WPH;
    constexpr int NT   = (P==2) ? 130 : 88;
    constexpr int PADL = (P==2) ? 2 : 5;
    constexpr int LW   = (P==2) ? 12 : 28;   // padded weight row (mult of 4)
    constexpr int SEC  = (P==2) ? 4 : 12;    // padded section length
    constexpr int HSTR = 3*SEC, TSTR = HC*HSTR;
    constexpr int MROW = NH*9*PP;            // total weight rows
    constexpr int NTILES = 4*NT*NT;
    constexpr int NTH = NWARPS*32;
    constexpr float RS = ((P==2) ? 0.2886751345948129f : 0.1924500897298753f) * LOG2E;

    __shared__ __align__(16) float swt[MROW*LW];
    __shared__ float sb[MROW];               // used only for P==2
    __shared__ float sxt[LW][32];            // transposed: [l][tile-lane]

    const float* Xg = (P==2) ? g_x3 : g_x6;
    float* scr      = (P==2) ? g_scr2 : g_scr3;

    const int tid = threadIdx.x;
    const int warp = tid >> 5, lane = tid & 31;
    const int t0 = blockIdx.x * 32;

    // weights into padded smem; for P==3 the pad column L(=27) carries the bias
    for (int idx = tid; idx < MROW*LW; idx += NTH) {
        int m = idx / LW, lp = idx % LW;
        float v = 0.f;
        if (lp < L) v = W[m*L + lp];
        else if (P == 3 && lp == L) v = B[m];
        swt[idx] = v;
    }
    if (P == 2) {
        for (int idx = tid; idx < MROW; idx += NTH) sb[idx] = B[idx];
    }
    // x tile rows, transposed so lane reads are conflict-free
    for (int idx = tid; idx < LW*32; idx += NTH) {
        int lp = idx >> 5, lane2 = idx & 31;
        int t = t0 + lane2;
        float v = 0.f;
        if (t < NTILES && lp < L) {
            int tj = t % NT, ti = (t / NT) % NT, b = t / (NT*NT);
            int cc = lp / PP, rr = (lp % PP) / P, ss = lp % P;
            int y  = reflect256(ti*P + rr - PADL);
            int x2 = reflect256(tj*P + ss - PADL);
            v = Xg[(b*3+cc)*65536 + y*256 + x2];
        }
        sxt[lp][lane2] = v;
    }
    __syncthreads();

    const int t = t0 + lane;
    const bool active = (t < NTILES);

    float xr[LW];
    #pragma unroll
    for (int l = 0; l < LW; l++) xr[l] = sxt[l][lane];
    if (P == 3) xr[L] = 1.0f;   // bias multiplier (weight pad column carries B)

    #pragma unroll
    for (int u = 0; u < WPH; u++) {
        const int hc = warp + u*NWARPS;
        const int h = hc % NH, c = hc / NH;
        float* outb = scr + (size_t)t*TSTR + hc*HSTR;

        #pragma unroll
        for (int sec = 0; sec < 3; sec++) {
            const int row0 = ((h*3 + sec)*3 + c)*PP;
            float acc[SEC];
            #pragma unroll
            for (int pos = 0; pos < SEC; pos++) acc[pos] = 0.f;
            #pragma unroll
            for (int pos = 0; pos < PP; pos++) {
                float a;
                if (P == 3) {
                    // 4 independent partial chains; bias rides chain 3 via xr[27]=1
                    float a0 = 0.f, a1 = 0.f, a2 = 0.f, a3 = 0.f;
                    #pragma unroll
                    for (int l4 = 0; l4 < LW/4; l4++) {
                        float4 w4 = *(const float4*)&swt[(row0+pos)*LW + l4*4];  // broadcast
                        a0 += w4.x*xr[l4*4+0];
                        a1 += w4.y*xr[l4*4+1];
                        a2 += w4.z*xr[l4*4+2];
                        a3 += w4.w*xr[l4*4+3];
                    }
                    a = (a0 + a1) + (a2 + a3);
                } else {
                    a = sb[row0 + pos];
                    #pragma unroll
                    for (int l4 = 0; l4 < LW/4; l4++) {
                        float4 w4 = *(const float4*)&swt[(row0+pos)*LW + l4*4];  // broadcast
                        a += w4.x*xr[l4*4+0] + w4.y*xr[l4*4+1]
                           + w4.z*xr[l4*4+2] + w4.w*xr[l4*4+3];
                    }
                }
                acc[pos] = (sec == 0) ? a*RS : a;
            }
            if (active) {
                #pragma unroll
                for (int s4 = 0; s4 < SEC/4; s4++) {
                    float4 o4;
                    o4.x = acc[s4*4+0]; o4.y = acc[s4*4+1];
                    o4.z = acc[s4*4+2]; o4.w = acc[s4*4+3];
                    *(float4*)&outb[sec*SEC + s4*4] = o4;
                }
            }
        }
    }
}

// ---- stages 2/3: attention kernel. block = 4x4 window patch, thread = (window, hc). ----
template<int P, int NH>
__global__ __launch_bounds__(16*NH*3) void attn_win_kernel(const float* __restrict__ HW)
{
    constexpr int PP = P*P, HC = NH*3;
    constexpr int NT   = (P==2) ? 130 : 88;
    constexpr int NHW  = (P==2) ? 128 : 86;
    constexpr int PADH = (P==2) ? 0 : 2;
    constexpr int SEC  = (P==2) ? 4 : 12;
    constexpr int HSTR = 3*SEC, TSTR = HC*HSTR;
    constexpr int NTH = 16*HC;

    __shared__ __align__(16) float st[36*TSTR];

    const float* scr = (P==2) ? g_scr2 : g_scr3;
    float* Og        = (P==2) ? g_x6 : g_x9;

    const int tid = threadIdx.x;
    const int wi0 = blockIdx.y * 4, wj0 = blockIdx.x * 4;
    const int b = blockIdx.z;

    // cooperative load of 6x6 tile qkv block (float4 granularity)
    for (int f4 = tid; f4 < 36*(TSTR/4); f4 += NTH) {
        int tile_l = f4 / (TSTR/4), rem = f4 % (TSTR/4);
        int u = tile_l / 6, v = tile_l % 6;
        int ti = wi0 + u, tj = wj0 + v;
        float4 val = make_float4(0.f, 0.f, 0.f, 0.f);
        if (ti < NT && tj < NT)
            val = *(const float4*)&scr[(size_t)((b*NT + ti)*NT + tj)*TSTR + rem*4];
        *(float4*)&st[tile_l*TSTR + rem*4] = val;
    }
    __syncthreads();

    const int hc = tid % HC, wl = tid / HC;
    const int h = hc % NH;
    const int c = hc / NH;
    const int wl4 = wl >> 2, wlm = wl & 3;
    const int wi = wi0 + wl4, wj = wj0 + wlm;
    const bool active = (wi < NHW) && (wj < NHW);

    // q of core tile (pre-scaled by log2e/sqrt(L))
    const float* core = st + ((wl4+1)*6 + (wlm+1))*TSTR + hc*HSTR;
    float q[SEC];
    #pragma unroll
    for (int s4 = 0; s4 < SEC/4; s4++)
        *(float4*)&q[s4*4] = *(const float4*)&core[s4*4];

    // qe[di][pos] = q[pos] * exp(-u/P), u = f(di, ii)
    float qe[3][PP];
    #pragma unroll
    for (int pos = 0; pos < PP; pos++) {
        const int ii = pos / P;
        qe[0][pos] = q[pos] * ebias<P>(P-1-ii);
        qe[1][pos] = q[pos];
        qe[2][pos] = q[pos] * ebias<P>(ii);
    }

    float score[9];
    #pragma unroll
    for (int k9 = 0; k9 < 9; k9++) {
        const int di = k9/3, dj = k9%3;
        const float* kt = st + ((wl4+di)*6 + (wlm+dj))*TSTR + hc*HSTR + SEC;
        float kv[SEC];
        #pragma unroll
        for (int s4 = 0; s4 < SEC/4; s4++)
            *(float4*)&kv[s4*4] = *(const float4*)&kt[s4*4];
        float s = 0.f;
        #pragma unroll
        for (int pos = 0; pos < PP; pos++) {
            const int jj = pos % P;
            const float ev = (dj==0) ? ebias<P>(P-1-jj) : ((dj==1) ? 1.f : ebias<P>(jj));
            s += qe[di][pos] * (ev * kv[pos]);
        }
        score[k9] = ex2(s);   // exp(raw score), log2e pre-folded into q
    }

    float sum = 0.f;
    #pragma unroll
    for (int k = 0; k < 9; k++) sum += score[k];
    const float hwv = __fdividef(__ldg(HW + h), sum);

    float outp[PP];
    #pragma unroll
    for (int pos = 0; pos < PP; pos++) outp[pos] = 0.f;
    #pragma unroll
    for (int k9 = 0; k9 < 9; k9++) {
        const float* vt = st + ((wl4 + k9/3)*6 + (wlm + k9%3))*TSTR + hc*HSTR + 2*SEC;
        float vv[SEC];
        #pragma unroll
        for (int s4 = 0; s4 < SEC/4; s4++)
            *(float4*)&vv[s4*4] = *(const float4*)&vt[s4*4];
        #pragma unroll
        for (int pos = 0; pos < PP; pos++) outp[pos] += score[k9] * vv[pos];
    }
    #pragma unroll
    for (int pos = 0; pos < PP; pos++) outp[pos] *= hwv;

    // head reduction over NH adjacent lanes (aligned groups)
    #pragma unroll
    for (int pos = 0; pos < PP; pos++) {
        outp[pos] += __shfl_xor_sync(0xffffffffu, outp[pos], 1);
        if (NH == 4) outp[pos] += __shfl_xor_sync(0xffffffffu, outp[pos], 2);
    }

    if (h == 0 && active) {
        #pragma unroll
        for (int pos = 0; pos < PP; pos++) {
            const int y  = wi*P + pos/P - PADH;
            const int x2 = wj*P + pos%P - PADH;
            if (y >= 0 && x2 >= 0)
                Og[(b*3+c)*65536 + y*256 + x2] = outp[pos];
        }
    }
}

// 5x5 conv (9->3 channels) fused with the final elementwise gate
__global__ __launch_bounds__(128) void conv_final_kernel(
    const float* __restrict__ X, const float* __restrict__ CW,
    const float* __restrict__ CB, float* __restrict__ out)
{
    __shared__ float sx[9][20][37];
    __shared__ float sw[675];
    __shared__ float sb[3];
    const int b = blockIdx.z;
    const int x0 = blockIdx.x * 32, y0 = blockIdx.y * 16;
    const int tid = threadIdx.x;

    for (int i2 = tid; i2 < 675; i2 += 128) sw[i2] = CW[i2];
    if (tid < 3) sb[tid] = CB[tid];
    for (int i2 = tid; i2 < 9*20*36; i2 += 128) {
        int ci = i2 / 720, rem = i2 % 720, yy = rem / 36, xx = rem % 36;
        int gy = y0 + yy - 2, gx = x0 + xx - 2;
        float v = 0.f;
        if ((unsigned)gy < 256u && (unsigned)gx < 256u) {
            const float* src = (ci < 3) ? g_x9 : ((ci < 6) ? g_x6 : g_x3);
            v = src[(b*3 + (ci % 3))*65536 + gy*256 + gx];
        }
        sx[ci][yy][xx] = v;
    }
    __syncthreads();

    const int tx = tid & 15, ty = tid >> 4;
    const int lx = tx*2, ly = ty*2;
    float acc[3][4];
    #pragma unroll
    for (int c2 = 0; c2 < 3; c2++)
        #pragma unroll
        for (int p2 = 0; p2 < 4; p2++) acc[c2][p2] = 0.f;

    #pragma unroll 1
    for (int ci = 0; ci < 9; ci++) {
        #pragma unroll
        for (int ky = 0; ky < 5; ky++) {
            #pragma unroll
            for (int kx = 0; kx < 5; kx++) {
                float w0 = sw[      ci*25 + ky*5 + kx];
                float w1 = sw[225 + ci*25 + ky*5 + kx];
                float w2 = sw[450 + ci*25 + ky*5 + kx];
                float a00 = sx[ci][ly+ky  ][lx+kx  ];
                float a01 = sx[ci][ly+ky  ][lx+kx+1];
                float a10 = sx[ci][ly+ky+1][lx+kx  ];
                float a11 = sx[ci][ly+ky+1][lx+kx+1];
                acc[0][0] += w0*a00; acc[0][1] += w0*a01; acc[0][2] += w0*a10; acc[0][3] += w0*a11;
                acc[1][0] += w1*a00; acc[1][1] += w1*a01; acc[1][2] += w1*a10; acc[1][3] += w1*a11;
                acc[2][0] += w2*a00; acc[2][1] += w2*a01; acc[2][2] += w2*a10; acc[2][3] += w2*a11;
            }
        }
    }

    const float xg = g_xg[b];
    #pragma unroll
    for (int co = 0; co < 3; co++) {
        #pragma unroll
        for (int py = 0; py < 2; py++) {
            #pragma unroll
            for (int px = 0; px < 2; px++) {
                int gy = y0 + ly + py, gx = x0 + lx + px;
                float x0v = fmaxf(acc[co][py*2+px] + sb[co], 0.f);
                float xv = X[(b*3+co)*65536 + gy*256 + gx];
                float r = fmaxf(xv * x0v + xg - x0v, 0.f);
                out[(b*3+co)*65536 + gy*256 + gx] = r;
            }
        }
    }
}

extern "C" void kernel_launch(void* const* d_in, const int* in_sizes, int n_in,
                              void* d_out, int out_size) {
    (void)in_sizes; (void)n_in; (void)out_size;
    const float* x   = (const float*)d_in[0];
    const float* w3  = (const float*)d_in[1];
    const float* b3  = (const float*)d_in[2];
    const float* hw3 = (const float*)d_in[3];
    const float* w6  = (const float*)d_in[4];
    const float* b6  = (const float*)d_in[5];
    const float* hw6 = (const float*)d_in[6];
    const float* w9  = (const float*)d_in[7];
    const float* b9  = (const float*)d_in[8];
    const float* hw9 = (const float*)d_in[9];
    const float* cw  = (const float*)d_in[10];
    const float* cb  = (const float*)d_in[11];
    float* out = (float*)d_out;

    // reset g_xg (x >= 0 so zero-init is a valid identity for max)
    void* xg_ptr = nullptr;
    cudaGetSymbolAddress(&xg_ptr, g_xg);
    cudaMemsetAsync(xg_ptr, 0, 4*sizeof(float));

    attn1_kernel<<<8192, 192>>>(x, w3, b3, hw3);

    // stage 2: P=2, NH=4. 67600 tiles -> 2113 blocks of 32 tiles, 12 warps (WPH=1)
    proj_kernel<2, 4, 1><<<(67600 + 31) / 32, 12*32>>>(w6, b6);
    attn_win_kernel<2, 4><<<dim3(32, 32, 4), 16*12>>>(hw6);

    // stage 3: P=3, NH=2. 30976 tiles -> 968 blocks of 32 tiles, 3 warps (WPH=2)
    proj_kernel<3, 2, 2><<<30976/32, 3*32>>>(w9, b9);
    attn_win_kernel<3, 2><<<dim3(22, 22, 4), 16*6>>>(hw9);

    conv_final_kernel<<<dim3(8, 16, 4), 128>>>(x, cw, cb, out);
}